// round 16
// baseline (speedup 1.0000x reference)
#include <cuda_runtime.h>
#include <cuda_bf16.h>
#include <cstdint>
#include <math.h>

// ---------------------------------------------------------------------------
// MoE: B=4,S=2048,D=1024,H=4096,E=8,top2. T=8192.
// HMMA bf16 split GEMMs (Ah*Bh + Ah*Bl + Al*Bh), in-kernel fp32->bf16 split.
// R16: TRIPLE-buffered stages (3 x 16KB = 48KB static cap). KSTEP(s) reads
// data stored two barriers ago -> STS->ldm latency off the critical path
// (R15 counters: nothing saturated => latency-bound at 4 warps/SMSP).
// CTA 128x128, BK=16, 8 warps (2Mx4N, warp 64x32), B n-major (no .trans).
// Envelope: static smem <= 48KB, no cudaFuncSetAttribute, no cp.async,
// no lambdas, no dynamic local indexing, globals ~320MB.
// ---------------------------------------------------------------------------

#define D_DIM 1024
#define H_DIM 4096
#define NE    8
#define MAXT  8192
#define MAXSLOT (MAXT * 2)
#define MAXRBLK (MAXT / 8)

__device__ float g_partp[MAXRBLK * NE];
__device__ int   g_partc[MAXRBLK * NE];
__device__ float g_psum[NE];
__device__ int   g_cnt[NE];
__device__ int   g_off[NE + 1];
__device__ int   g_cur[NE];
__device__ int   g_idx2[MAXT * 2];
__device__ float g_w2[MAXT * 2];
__device__ int   g_slot[MAXT * 2];
__device__ int   g_tok[MAXSLOT];
__device__ float g_Hbuf[(size_t)MAXSLOT * H_DIM];  // 256 MB fp32
__device__ float g_Ybuf[(size_t)MAXSLOT * D_DIM];  // 64 MB fp32

// ------------------------------- helpers -----------------------------------
__device__ __forceinline__ uint32_t smem_u32(const void* p) {
    uint32_t a;
    asm("{ .reg .u64 t; cvta.to.shared.u64 t, %1; cvt.u32.u64 %0, t; }"
        : "=r"(a) : "l"(p));
    return a;
}
__device__ __forceinline__ void ldm_x4(uint32_t& r0, uint32_t& r1,
                                       uint32_t& r2, uint32_t& r3, uint32_t addr) {
    asm volatile("ldmatrix.sync.aligned.m8n8.x4.shared.b16 {%0,%1,%2,%3}, [%4];\n"
                 : "=r"(r0), "=r"(r1), "=r"(r2), "=r"(r3) : "r"(addr));
}
__device__ __forceinline__ void mma16816(float& d0, float& d1, float& d2, float& d3,
                                         uint32_t a0, uint32_t a1, uint32_t a2, uint32_t a3,
                                         uint32_t b0, uint32_t b1) {
    asm volatile(
        "mma.sync.aligned.m16n8k16.row.col.f32.bf16.bf16.f32 "
        "{%0,%1,%2,%3}, {%4,%5,%6,%7}, {%8,%9}, {%0,%1,%2,%3};\n"
        : "+f"(d0), "+f"(d1), "+f"(d2), "+f"(d3)
        : "r"(a0), "r"(a1), "r"(a2), "r"(a3), "r"(b0), "r"(b1));
}
__device__ __forceinline__ void sts16(uint32_t addr, uint32_t x, uint32_t y,
                                      uint32_t z, uint32_t w) {
    asm volatile("st.shared.v4.b32 [%0], {%1,%2,%3,%4};\n"
                 :: "r"(addr), "r"(x), "r"(y), "r"(z), "r"(w) : "memory");
}
// Tile layout (A and B identical): 128 rows x 16 bf16 = 32B/row, packed
// 2 rows per 64B line. sub = (row&1)*2 + c, phys = sub ^ ((row>>2)&1).
// Conflict-free for STS.128 and ldmatrix (granules distinct mod 8).
__device__ __forceinline__ uint32_t a16_off(int row, int c) {
    int sub = (row & 1) * 2 + c;
    return (uint32_t)(((row >> 1) * 4 + (sub ^ ((row >> 2) & 1))) << 4);
}
// fast split: 2 floats -> bf16x2 hi + bf16x2 lo (6 ops)
__device__ __forceinline__ void split2(float v0, float v1, uint32_t& h, uint32_t& l) {
    uint32_t hv, h0b, h1b;
    asm("cvt.rn.bf16x2.f32 %0, %1, %2;" : "=r"(hv) : "f"(v1), "f"(v0));
    asm("prmt.b32 %0, %1, 0, 0x1044;" : "=r"(h0b) : "r"(hv));   // h0 << 16
    asm("prmt.b32 %0, %1, 0, 0x3244;" : "=r"(h1b) : "r"(hv));   // h1 << 16
    float l0 = v0 - __uint_as_float(h0b);
    float l1 = v1 - __uint_as_float(h1b);
    asm("cvt.rn.bf16x2.f32 %0, %1, %2;" : "=r"(l) : "f"(l1), "f"(l0));
    h = hv;
}
__device__ __forceinline__ float gelu_f(float v) {
    return 0.5f * v * (1.0f + erff(v * 0.7071067811865476f));
}

// ------------------------------- router ------------------------------------
__global__ __launch_bounds__(256) void router_kernel(
    const float* __restrict__ x, const float* __restrict__ Wg, int T)
{
    __shared__ float sp[8][NE];
    __shared__ int   si[8][2];
    int tid = threadIdx.x, warp = tid >> 5, lane = tid & 31;
    int t = blockIdx.x * 8 + warp;

    float acc[NE];
#pragma unroll
    for (int e = 0; e < NE; e++) acc[e] = 0.f;
    if (t < T) {
        const float* xr = x + (size_t)t * D_DIM;
        for (int d = lane; d < D_DIM; d += 32) {
            float xv = xr[d];
            const float* wr = Wg + d * NE;
#pragma unroll
            for (int e = 0; e < NE; e++) acc[e] += xv * wr[e];
        }
    }
#pragma unroll
    for (int e = 0; e < NE; e++)
#pragma unroll
        for (int o = 16; o > 0; o >>= 1)
            acc[e] += __shfl_xor_sync(0xFFFFFFFFu, acc[e], o);

    if (lane == 0) {
        if (t < T) {
            float m = acc[0];
#pragma unroll
            for (int e = 1; e < NE; e++) m = fmaxf(m, acc[e]);
            float p[NE]; float s = 0.f;
#pragma unroll
            for (int e = 0; e < NE; e++) { p[e] = expf(acc[e] - m); s += p[e]; }
            float inv = 1.0f / s;
#pragma unroll
            for (int e = 0; e < NE; e++) p[e] *= inv;
            int i0 = 0; float v0 = p[0];
#pragma unroll
            for (int e = 1; e < NE; e++)
                if (p[e] > v0) { v0 = p[e]; i0 = e; }
            int i1 = -1; float v1 = -1.f;
#pragma unroll
            for (int e = 0; e < NE; e++) {
                if (e == i0) continue;
                if (p[e] > v1) { v1 = p[e]; i1 = e; }
            }
            float ws = v0 + v1;
            g_idx2[2 * t] = i0;  g_idx2[2 * t + 1] = i1;
            g_w2[2 * t] = v0 / ws;  g_w2[2 * t + 1] = v1 / ws;
#pragma unroll
            for (int e = 0; e < NE; e++) sp[warp][e] = p[e];
            si[warp][0] = i0; si[warp][1] = i1;
        } else {
#pragma unroll
            for (int e = 0; e < NE; e++) sp[warp][e] = 0.f;
            si[warp][0] = -1; si[warp][1] = -1;
        }
    }
    __syncthreads();
    if (tid < NE) {
        float s = 0.f; int c = 0;
#pragma unroll
        for (int w = 0; w < 8; w++) {
            s += sp[w][tid];
            if (si[w][0] == tid || si[w][1] == tid) c++;
        }
        g_partp[blockIdx.x * NE + tid] = s;
        g_partc[blockIdx.x * NE + tid] = c;
    }
}

__global__ void reduce_kernel(int nblk, int T, float* __restrict__ aux_out) {
    int tid = threadIdx.x;
    if (tid < NE) {
        float ps = 0.f; int cs = 0;
        for (int b = 0; b < nblk; b++) {
            ps += g_partp[b * NE + tid];
            cs += g_partc[b * NE + tid];
        }
        g_psum[tid] = ps; g_cnt[tid] = cs; g_cur[tid] = 0;
    }
    __syncthreads();
    if (tid == 0) {
        int off = 0;
        for (int e = 0; e < NE; e++) { g_off[e] = off; off += g_cnt[e]; }
        g_off[NE] = off;
        float invT = 1.0f / (float)T;
        float aux = 0.f;
        for (int e = 0; e < NE; e++)
            aux += ((float)g_cnt[e] * invT) * (g_psum[e] * invT);
        *aux_out = (float)NE * aux;
    }
}

__global__ void scatter_kernel(int T) {
    int t = blockIdx.x * 256 + threadIdx.x;
    if (t >= T) return;
#pragma unroll
    for (int k = 0; k < 2; k++) {
        int e = g_idx2[2 * t + k];
        int pos = atomicAdd(&g_cur[e], 1);
        int s = g_off[e] + pos;
        g_tok[s] = t;
        g_slot[2 * t + k] = s;
    }
}

// --------------------------- HMMA grouped GEMM -----------------------------
// CTA 128(M) x 128(N), BK=16. 8 warps (2Mx4N), warp tile 64x32.
// TRIPLE-buffered smem 3 x 16KB; stage: Ah 4K | Al 4K | Bh 4K | Bl 4K.
// iter s: STORES(stage s+2 -> bW); LOADG(stage s+3); KSTEP(stage s, bR);
// bar; rotate(bR,bM,bW). KSTEP reads data stored two barriers earlier.
#define BUF_BYTES 16384

#define LOADG() do {                                                          \
    ra0 = *(const float4*)(pA);                                               \
    ra1 = *(const float4*)(pA + 4);                                           \
    rb0 = pB[0];                                                              \
    rb1 = pB[(size_t)NTOT];                                                   \
    rb2 = pB[(size_t)2 * NTOT];                                               \
    rb3 = pB[(size_t)3 * NTOT];                                               \
    rb4 = pB[(size_t)4 * NTOT];                                               \
    rb5 = pB[(size_t)5 * NTOT];                                               \
    rb6 = pB[(size_t)6 * NTOT];                                               \
    rb7 = pB[(size_t)7 * NTOT];                                               \
    pA += 16;  pB += (size_t)16 * NTOT;                                       \
} while (0)

#define STORES(BB) do {                                                       \
    uint32_t h0_,h1_,h2_,h3_, l0_,l1_,l2_,l3_;                                \
    split2(ra0.x, ra0.y, h0_, l0_);  split2(ra0.z, ra0.w, h1_, l1_);          \
    split2(ra1.x, ra1.y, h2_, l2_);  split2(ra1.z, ra1.w, h3_, l3_);          \
    sts16((BB) + sAo, h0_, h1_, h2_, h3_);                                    \
    sts16((BB) + 4096 + sAo, l0_, l1_, l2_, l3_);                             \
    split2(rb0, rb1, h0_, l0_);  split2(rb2, rb3, h1_, l1_);                  \
    split2(rb4, rb5, h2_, l2_);  split2(rb6, rb7, h3_, l3_);                  \
    sts16((BB) + 8192 + sBo, h0_, h1_, h2_, h3_);                             \
    sts16((BB) + 12288 + sBo, l0_, l1_, l2_, l3_);                            \
} while (0)

// Term-major MMA order per m-tile: term-h j0..3, term-bl j0..3, term-al j0..3.
// Accumulation order per acc unchanged (h, bl, al) -> bitwise-identical.
#define MMAROW(I)                                                                             \
    mma16816(acc[I][0][0],acc[I][0][1],acc[I][0][2],acc[I][0][3], a0,a1,a2,a3, u0,u1);        \
    mma16816(acc[I][1][0],acc[I][1][1],acc[I][1][2],acc[I][1][3], a0,a1,a2,a3, u2,u3);        \
    mma16816(acc[I][2][0],acc[I][2][1],acc[I][2][2],acc[I][2][3], a0,a1,a2,a3, u4,u5);        \
    mma16816(acc[I][3][0],acc[I][3][1],acc[I][3][2],acc[I][3][3], a0,a1,a2,a3, u6,u7);        \
    mma16816(acc[I][0][0],acc[I][0][1],acc[I][0][2],acc[I][0][3], a0,a1,a2,a3, w0,w1);        \
    mma16816(acc[I][1][0],acc[I][1][1],acc[I][1][2],acc[I][1][3], a0,a1,a2,a3, w2,w3);        \
    mma16816(acc[I][2][0],acc[I][2][1],acc[I][2][2],acc[I][2][3], a0,a1,a2,a3, w4,w5);        \
    mma16816(acc[I][3][0],acc[I][3][1],acc[I][3][2],acc[I][3][3], a0,a1,a2,a3, w6,w7);        \
    mma16816(acc[I][0][0],acc[I][0][1],acc[I][0][2],acc[I][0][3], c0,c1,c2,c3, u0,u1);        \
    mma16816(acc[I][1][0],acc[I][1][1],acc[I][1][2],acc[I][1][3], c0,c1,c2,c3, u2,u3);        \
    mma16816(acc[I][2][0],acc[I][2][1],acc[I][2][2],acc[I][2][3], c0,c1,c2,c3, u4,u5);        \
    mma16816(acc[I][3][0],acc[I][3][1],acc[I][3][2],acc[I][3][3], c0,c1,c2,c3, u6,u7);

#define KSTEP16(BB) do {                                                      \
    uint32_t u0,u1,u2,u3,u4,u5,u6,u7, w0,w1,w2,w3,w4,w5,w6,w7;                \
    ldm_x4(u0,u1,u2,u3, (BB) + 8192 + offB0);                                 \
    ldm_x4(u4,u5,u6,u7, (BB) + 8192 + offB1);                                 \
    ldm_x4(w0,w1,w2,w3, (BB) + 12288 + offB0);                                \
    ldm_x4(w4,w5,w6,w7, (BB) + 12288 + offB1);                                \
    {   uint32_t a0,a1,a2,a3, c0,c1,c2,c3;                                    \
        ldm_x4(a0,a1,a2,a3, (BB) + offA0);                                    \
        ldm_x4(c0,c1,c2,c3, (BB) + 4096 + offA0);                             \
        MMAROW(0)                                                             \
    }                                                                         \
    {   uint32_t a0,a1,a2,a3, c0,c1,c2,c3;                                    \
        ldm_x4(a0,a1,a2,a3, (BB) + offA1);                                    \
        ldm_x4(c0,c1,c2,c3, (BB) + 4096 + offA1);                             \
        MMAROW(1)                                                             \
    }                                                                         \
    {   uint32_t a0,a1,a2,a3, c0,c1,c2,c3;                                    \
        ldm_x4(a0,a1,a2,a3, (BB) + offA2);                                    \
        ldm_x4(c0,c1,c2,c3, (BB) + 4096 + offA2);                             \
        MMAROW(2)                                                             \
    }                                                                         \
    {   uint32_t a0,a1,a2,a3, c0,c1,c2,c3;                                    \
        ldm_x4(a0,a1,a2,a3, (BB) + offA3);                                    \
        ldm_x4(c0,c1,c2,c3, (BB) + 4096 + offA3);                             \
        MMAROW(3)                                                             \
    }                                                                         \
} while (0)

template <int KDIM, int NTOT, bool FIRST>
__global__ __launch_bounds__(256, 2) void moe_gemm_mma(
    const float* __restrict__ xsrc,      // x for FIRST (else unused)
    const float* __restrict__ W,         // [E][KDIM][NTOT] fp32
    const float* __restrict__ bias)      // [E][NTOT] fp32
{
    constexpr int NS = KDIM / 16;
    int e = blockIdx.z;
    int seg0 = g_off[e];
    int M = g_off[e + 1] - seg0;
    int rowTile = blockIdx.y * 128;       // colTile-fastest grid (L2 reuse)
    if (rowTile >= M) return;
    int colTile = blockIdx.x * 128;

    __shared__ __align__(128) char sbuf[3][BUF_BYTES];   // exactly 48 KB

    int tid = threadIdx.x, wid = tid >> 5, lane = tid & 31;
    const float* srcA = FIRST ? xsrc : g_Hbuf;

    // ---- per-thread loader constants ----
    // A: row = tid>>1 (0..127), k-half = tid&1 (8 floats, 2 float4)
    int arow = tid >> 1, ac = tid & 1;
    int rA_g = rowTile + arow;
    int groff;
    if (FIRST) {
        groff = ((rA_g < M) ? g_tok[seg0 + rA_g] : g_tok[seg0]) * KDIM;
    } else {
        groff = (seg0 + ((rA_g < M) ? rA_g : 0)) * KDIM;
    }
    const float* pA = srcA + groff + ac * 8;
    uint32_t sAo = a16_off(arow, ac);
    // B (n-major gather): n = tid>>1 (0..127), k-half = tid&1 -> 8 strided
    // scalar loads (coalesced across the warp).
    int bn = tid >> 1, bkh = tid & 1;
    const float* pB = W + ((size_t)e * KDIM + bkh * 8) * NTOT + colTile + bn;
    uint32_t sBo = a16_off(bn, bkh);

    // ---- ldmatrix offsets ----
    int warpM = (wid & 1) * 64;
    int warpN = (wid >> 1) * 32;
    int lrow = lane & 15, lch = lane >> 4;
    uint32_t offA0 = a16_off(warpM + 0  + lrow, lch);
    uint32_t offA1 = a16_off(warpM + 16 + lrow, lch);
    uint32_t offA2 = a16_off(warpM + 32 + lrow, lch);
    uint32_t offA3 = a16_off(warpM + 48 + lrow, lch);
    // B non-trans: {r0,r1} = n0-7 frag, {r2,r3} = n8-15 frag.
    int brow = (lane & 7) + ((lane >> 4) << 3);
    int bch = (lane >> 3) & 1;
    uint32_t offB0 = a16_off(warpN + brow, bch);
    uint32_t offB1 = a16_off(warpN + 16 + brow, bch);

    float acc[4][4][4];
#pragma unroll
    for (int i = 0; i < 4; i++)
#pragma unroll
        for (int j = 0; j < 4; j++)
#pragma unroll
            for (int q = 0; q < 4; q++) acc[i][j][q] = 0.f;

    uint32_t sb0 = smem_u32(sbuf);
    uint32_t bR = sb0;                    // read buffer  (stage s)
    uint32_t bM = sb0 + BUF_BYTES;        // mid buffer   (stage s+1)
    uint32_t bW = sb0 + 2 * BUF_BYTES;    // write buffer (stage s+2)
    float4 ra0, ra1;
    float rb0, rb1, rb2, rb3, rb4, rb5, rb6, rb7;

    // prologue: stage0->b0, stage1->b1, stage2 in regs
    LOADG();
    STORES(bR);
    LOADG();
    STORES(bM);
    LOADG();
    __syncthreads();

    for (int s = 0; s < NS; s++) {
        if (s + 2 < NS) STORES(bW);
        if (s + 3 < NS) LOADG();
        KSTEP16(bR);
        __syncthreads();
        uint32_t t_ = bR; bR = bM; bM = bW; bW = t_;   // rotate (regs only)
    }

    // ----- epilogue -----
    const float* bcolBase = bias + (size_t)e * NTOT + colTile;
#pragma unroll
    for (int i = 0; i < 4; i++) {
        int r0e = warpM + i * 16 + (lane >> 2);
#pragma unroll
        for (int h = 0; h < 2; h++) {
            int grow = rowTile + r0e + h * 8;
            if (grow >= M) continue;
            size_t orow = (size_t)(seg0 + grow) * NTOT + colTile;
#pragma unroll
            for (int j = 0; j < 4; j++) {
                int col = warpN + j * 8 + (lane & 3) * 2;
                float v0 = acc[i][j][2 * h]     + bcolBase[col];
                float v1 = acc[i][j][2 * h + 1] + bcolBase[col + 1];
                if (FIRST) {
                    v0 = gelu_f(v0); v1 = gelu_f(v1);
                    *(float2*)(g_Hbuf + orow + col) = make_float2(v0, v1);
                } else {
                    *(float2*)(g_Ybuf + orow + col) = make_float2(v0, v1);
                }
            }
        }
    }
}

// ------------------------------- combine -----------------------------------
__global__ __launch_bounds__(256) void combine_kernel(float* __restrict__ out, int T) {
    size_t i = (size_t)blockIdx.x * 256 + threadIdx.x;
    size_t total = (size_t)T * (D_DIM / 4);
    if (i >= total) return;
    int t  = (int)(i >> 8);
    int d4 = (int)(i & 255);
    float w0 = g_w2[2 * t], w1 = g_w2[2 * t + 1];
    int s0 = g_slot[2 * t], s1 = g_slot[2 * t + 1];
    float4 a = ((const float4*)(g_Ybuf + (size_t)s0 * D_DIM))[d4];
    float4 b = ((const float4*)(g_Ybuf + (size_t)s1 * D_DIM))[d4];
    float4 o;
    o.x = w0 * a.x + w1 * b.x;
    o.y = w0 * a.y + w1 * b.y;
    o.z = w0 * a.z + w1 * b.z;
    o.w = w0 * a.w + w1 * b.w;
    ((float4*)(out + (size_t)t * D_DIM))[d4] = o;
}

// ------------------------------- launch ------------------------------------
extern "C" void kernel_launch(void* const* d_in, const int* in_sizes, int n_in,
                              void* d_out, int out_size)
{
    const float* x  = (const float*)d_in[0];
    const float* Wg = (const float*)d_in[1];
    const float* W1 = (const float*)d_in[2];
    const float* b1 = (const float*)d_in[3];
    const float* W2 = (const float*)d_in[4];
    const float* b2 = (const float*)d_in[5];
    float* out = (float*)d_out;

    int T = in_sizes[0] / D_DIM;
    if (T > MAXT) T = MAXT;

    int nblk = (T + 7) / 8;
    router_kernel<<<nblk, 256>>>(x, Wg, T);
    reduce_kernel<<<1, 32>>>(nblk, T, out + (size_t)T * D_DIM);
    scatter_kernel<<<(T + 255) / 256, 256>>>(T);

    int rowTilesMax = (T + 127) / 128;   // worst case: one expert takes all
    // colTile-fastest grid: concurrent CTAs share A/H rows; W stays in L2
    moe_gemm_mma<D_DIM, H_DIM, true ><<<dim3(H_DIM / 128, rowTilesMax, NE), 256>>>(x, W1, b1);
    moe_gemm_mma<H_DIM, D_DIM, false><<<dim3(D_DIM / 128, rowTilesMax, NE), 256>>>(nullptr, W2, b2);

    combine_kernel<<<(unsigned)(((size_t)T * 256 + 255) / 256), 256>>>(out, T);
}

// round 17
// speedup vs baseline: 1.4467x; 1.4467x over previous
#include <cuda_runtime.h>
#include <cuda_bf16.h>
#include <cstdint>
#include <math.h>

// ---------------------------------------------------------------------------
// MoE: B=4,S=2048,D=1024,H=4096,E=8,top2. T=8192.
// R17: 2-term FP16 split GEMMs:  A_h * B_h + A_h * B_l   (A_l*B dropped;
// fp16 tail ~2^-11 -> ~3-5e-4 total rel err, under the 1e-3 threshold).
// vs R15 (3-term bf16): -33% MMAs, -31% smem crossbar bytes, 12KB stages.
// CTA 128x128, BK=16, 8 warps (2Mx4N, warp 64x32), B n-major (no .trans),
// double-buffered 2x12KB. Envelope: static smem <= 48KB, no attrs/cp.async/
// lambdas/dynamic-local-indexing, globals ~320MB.
// ---------------------------------------------------------------------------

#define D_DIM 1024
#define H_DIM 4096
#define NE    8
#define MAXT  8192
#define MAXSLOT (MAXT * 2)
#define MAXRBLK (MAXT / 8)

__device__ float g_partp[MAXRBLK * NE];
__device__ int   g_partc[MAXRBLK * NE];
__device__ float g_psum[NE];
__device__ int   g_cnt[NE];
__device__ int   g_off[NE + 1];
__device__ int   g_cur[NE];
__device__ int   g_idx2[MAXT * 2];
__device__ float g_w2[MAXT * 2];
__device__ int   g_slot[MAXT * 2];
__device__ int   g_tok[MAXSLOT];
__device__ float g_Hbuf[(size_t)MAXSLOT * H_DIM];  // 256 MB fp32
__device__ float g_Ybuf[(size_t)MAXSLOT * D_DIM];  // 64 MB fp32

// ------------------------------- helpers -----------------------------------
__device__ __forceinline__ uint32_t smem_u32(const void* p) {
    uint32_t a;
    asm("{ .reg .u64 t; cvta.to.shared.u64 t, %1; cvt.u32.u64 %0, t; }"
        : "=r"(a) : "l"(p));
    return a;
}
__device__ __forceinline__ void ldm_x4(uint32_t& r0, uint32_t& r1,
                                       uint32_t& r2, uint32_t& r3, uint32_t addr) {
    asm volatile("ldmatrix.sync.aligned.m8n8.x4.shared.b16 {%0,%1,%2,%3}, [%4];\n"
                 : "=r"(r0), "=r"(r1), "=r"(r2), "=r"(r3) : "r"(addr));
}
__device__ __forceinline__ void mma16816(float& d0, float& d1, float& d2, float& d3,
                                         uint32_t a0, uint32_t a1, uint32_t a2, uint32_t a3,
                                         uint32_t b0, uint32_t b1) {
    asm volatile(
        "mma.sync.aligned.m16n8k16.row.col.f32.f16.f16.f32 "
        "{%0,%1,%2,%3}, {%4,%5,%6,%7}, {%8,%9}, {%0,%1,%2,%3};\n"
        : "+f"(d0), "+f"(d1), "+f"(d2), "+f"(d3)
        : "r"(a0), "r"(a1), "r"(a2), "r"(a3), "r"(b0), "r"(b1));
}
__device__ __forceinline__ void sts16(uint32_t addr, uint32_t x, uint32_t y,
                                      uint32_t z, uint32_t w) {
    asm volatile("st.shared.v4.b32 [%0], {%1,%2,%3,%4};\n"
                 :: "r"(addr), "r"(x), "r"(y), "r"(z), "r"(w) : "memory");
}
// Tile layout (A-hi / B-hi / B-lo identical): 128 rows x 16 f16 = 32B/row,
// packed 2 rows per 64B line. sub = (row&1)*2 + c, phys = sub^((row>>2)&1).
// Conflict-free for STS.128 and ldmatrix (granules distinct mod 8).
__device__ __forceinline__ uint32_t a16_off(int row, int c) {
    int sub = (row & 1) * 2 + c;
    return (uint32_t)(((row >> 1) * 4 + (sub ^ ((row >> 2) & 1))) << 4);
}
// fp16 pack (hi only): 2 floats -> f16x2 (lo half = v0)
__device__ __forceinline__ uint32_t cvt2h(float v0, float v1) {
    uint32_t h;
    asm("cvt.rn.f16x2.f32 %0, %1, %2;" : "=r"(h) : "f"(v1), "f"(v0));
    return h;
}
// fp16 split: 2 floats -> f16x2 hi + f16x2 lo
__device__ __forceinline__ void split2h(float v0, float v1, uint32_t& h, uint32_t& l) {
    asm("cvt.rn.f16x2.f32 %0, %1, %2;" : "=r"(h) : "f"(v1), "f"(v0));
    float h0, h1;
    asm("{ .reg .f16 lo, hi;\n\t"
        "mov.b32 {lo, hi}, %2;\n\t"
        "cvt.f32.f16 %0, lo;\n\t"
        "cvt.f32.f16 %1, hi; }"
        : "=f"(h0), "=f"(h1) : "r"(h));
    float l0 = v0 - h0, l1 = v1 - h1;
    asm("cvt.rn.f16x2.f32 %0, %1, %2;" : "=r"(l) : "f"(l1), "f"(l0));
}
__device__ __forceinline__ float gelu_f(float v) {
    return 0.5f * v * (1.0f + erff(v * 0.7071067811865476f));
}

// ------------------------------- router ------------------------------------
__global__ __launch_bounds__(256) void router_kernel(
    const float* __restrict__ x, const float* __restrict__ Wg, int T)
{
    __shared__ float sp[8][NE];
    __shared__ int   si[8][2];
    int tid = threadIdx.x, warp = tid >> 5, lane = tid & 31;
    int t = blockIdx.x * 8 + warp;

    float acc[NE];
#pragma unroll
    for (int e = 0; e < NE; e++) acc[e] = 0.f;
    if (t < T) {
        const float* xr = x + (size_t)t * D_DIM;
        for (int d = lane; d < D_DIM; d += 32) {
            float xv = xr[d];
            const float* wr = Wg + d * NE;
#pragma unroll
            for (int e = 0; e < NE; e++) acc[e] += xv * wr[e];
        }
    }
#pragma unroll
    for (int e = 0; e < NE; e++)
#pragma unroll
        for (int o = 16; o > 0; o >>= 1)
            acc[e] += __shfl_xor_sync(0xFFFFFFFFu, acc[e], o);

    if (lane == 0) {
        if (t < T) {
            float m = acc[0];
#pragma unroll
            for (int e = 1; e < NE; e++) m = fmaxf(m, acc[e]);
            float p[NE]; float s = 0.f;
#pragma unroll
            for (int e = 0; e < NE; e++) { p[e] = expf(acc[e] - m); s += p[e]; }
            float inv = 1.0f / s;
#pragma unroll
            for (int e = 0; e < NE; e++) p[e] *= inv;
            int i0 = 0; float v0 = p[0];
#pragma unroll
            for (int e = 1; e < NE; e++)
                if (p[e] > v0) { v0 = p[e]; i0 = e; }
            int i1 = -1; float v1 = -1.f;
#pragma unroll
            for (int e = 0; e < NE; e++) {
                if (e == i0) continue;
                if (p[e] > v1) { v1 = p[e]; i1 = e; }
            }
            float ws = v0 + v1;
            g_idx2[2 * t] = i0;  g_idx2[2 * t + 1] = i1;
            g_w2[2 * t] = v0 / ws;  g_w2[2 * t + 1] = v1 / ws;
#pragma unroll
            for (int e = 0; e < NE; e++) sp[warp][e] = p[e];
            si[warp][0] = i0; si[warp][1] = i1;
        } else {
#pragma unroll
            for (int e = 0; e < NE; e++) sp[warp][e] = 0.f;
            si[warp][0] = -1; si[warp][1] = -1;
        }
    }
    __syncthreads();
    if (tid < NE) {
        float s = 0.f; int c = 0;
#pragma unroll
        for (int w = 0; w < 8; w++) {
            s += sp[w][tid];
            if (si[w][0] == tid || si[w][1] == tid) c++;
        }
        g_partp[blockIdx.x * NE + tid] = s;
        g_partc[blockIdx.x * NE + tid] = c;
    }
}

__global__ void reduce_kernel(int nblk, int T, float* __restrict__ aux_out) {
    int tid = threadIdx.x;
    if (tid < NE) {
        float ps = 0.f; int cs = 0;
        for (int b = 0; b < nblk; b++) {
            ps += g_partp[b * NE + tid];
            cs += g_partc[b * NE + tid];
        }
        g_psum[tid] = ps; g_cnt[tid] = cs; g_cur[tid] = 0;
    }
    __syncthreads();
    if (tid == 0) {
        int off = 0;
        for (int e = 0; e < NE; e++) { g_off[e] = off; off += g_cnt[e]; }
        g_off[NE] = off;
        float invT = 1.0f / (float)T;
        float aux = 0.f;
        for (int e = 0; e < NE; e++)
            aux += ((float)g_cnt[e] * invT) * (g_psum[e] * invT);
        *aux_out = (float)NE * aux;
    }
}

__global__ void scatter_kernel(int T) {
    int t = blockIdx.x * 256 + threadIdx.x;
    if (t >= T) return;
#pragma unroll
    for (int k = 0; k < 2; k++) {
        int e = g_idx2[2 * t + k];
        int pos = atomicAdd(&g_cur[e], 1);
        int s = g_off[e] + pos;
        g_tok[s] = t;
        g_slot[2 * t + k] = s;
    }
}

// --------------------------- HMMA grouped GEMM -----------------------------
// CTA 128(M) x 128(N), BK=16. 8 warps (2Mx4N), warp tile 64x32.
// Per stage buffer (12KB): A-hi 4K @0 | B-hi 4K @4096 | B-lo 4K @8192.
// Double-buffered (2 x 12KB = 24KB). 2-term fp16 MMAs: Ah*Bh + Ah*Bl.
// iter s: STORES(stage s+1 -> other buf); LOADG(stage s+2); KSTEP(s); bar.
#define BUF_BYTES 12288

#define LOADG() do {                                                          \
    ra0 = *(const float4*)(pA);                                               \
    ra1 = *(const float4*)(pA + 4);                                           \
    rb0 = pB[0];                                                              \
    rb1 = pB[(size_t)NTOT];                                                   \
    rb2 = pB[(size_t)2 * NTOT];                                               \
    rb3 = pB[(size_t)3 * NTOT];                                               \
    rb4 = pB[(size_t)4 * NTOT];                                               \
    rb5 = pB[(size_t)5 * NTOT];                                               \
    rb6 = pB[(size_t)6 * NTOT];                                               \
    rb7 = pB[(size_t)7 * NTOT];                                               \
    pA += 16;  pB += (size_t)16 * NTOT;                                       \
} while (0)

#define STORES(BB) do {                                                       \
    uint32_t q0_ = cvt2h(ra0.x, ra0.y);                                       \
    uint32_t q1_ = cvt2h(ra0.z, ra0.w);                                       \
    uint32_t q2_ = cvt2h(ra1.x, ra1.y);                                       \
    uint32_t q3_ = cvt2h(ra1.z, ra1.w);                                       \
    sts16((BB) + sAo, q0_, q1_, q2_, q3_);                                    \
    uint32_t h0_,h1_,h2_,h3_, l0_,l1_,l2_,l3_;                                \
    split2h(rb0, rb1, h0_, l0_);  split2h(rb2, rb3, h1_, l1_);                \
    split2h(rb4, rb5, h2_, l2_);  split2h(rb6, rb7, h3_, l3_);                \
    sts16((BB) + 4096 + sBo, h0_, h1_, h2_, h3_);                             \
    sts16((BB) + 8192 + sBo, l0_, l1_, l2_, l3_);                             \
} while (0)

// Per m-tile: 4 n-tiles with B-hi, then 4 with B-lo (fixed accumulate order).
#define MMAROW(I)                                                                             \
    mma16816(acc[I][0][0],acc[I][0][1],acc[I][0][2],acc[I][0][3], a0,a1,a2,a3, u0,u1);        \
    mma16816(acc[I][1][0],acc[I][1][1],acc[I][1][2],acc[I][1][3], a0,a1,a2,a3, u2,u3);        \
    mma16816(acc[I][2][0],acc[I][2][1],acc[I][2][2],acc[I][2][3], a0,a1,a2,a3, u4,u5);        \
    mma16816(acc[I][3][0],acc[I][3][1],acc[I][3][2],acc[I][3][3], a0,a1,a2,a3, u6,u7);        \
    mma16816(acc[I][0][0],acc[I][0][1],acc[I][0][2],acc[I][0][3], a0,a1,a2,a3, w0,w1);        \
    mma16816(acc[I][1][0],acc[I][1][1],acc[I][1][2],acc[I][1][3], a0,a1,a2,a3, w2,w3);        \
    mma16816(acc[I][2][0],acc[I][2][1],acc[I][2][2],acc[I][2][3], a0,a1,a2,a3, w4,w5);        \
    mma16816(acc[I][3][0],acc[I][3][1],acc[I][3][2],acc[I][3][3], a0,a1,a2,a3, w6,w7);

#define KSTEP16(BB) do {                                                      \
    uint32_t u0,u1,u2,u3,u4,u5,u6,u7, w0,w1,w2,w3,w4,w5,w6,w7;                \
    ldm_x4(u0,u1,u2,u3, (BB) + 4096 + offB0);                                 \
    ldm_x4(u4,u5,u6,u7, (BB) + 4096 + offB1);                                 \
    ldm_x4(w0,w1,w2,w3, (BB) + 8192 + offB0);                                 \
    ldm_x4(w4,w5,w6,w7, (BB) + 8192 + offB1);                                 \
    {   uint32_t a0,a1,a2,a3;                                                 \
        ldm_x4(a0,a1,a2,a3, (BB) + offA0);                                    \
        MMAROW(0)                                                             \
    }                                                                         \
    {   uint32_t a0,a1,a2,a3;                                                 \
        ldm_x4(a0,a1,a2,a3, (BB) + offA1);                                    \
        MMAROW(1)                                                             \
    }                                                                         \
    {   uint32_t a0,a1,a2,a3;                                                 \
        ldm_x4(a0,a1,a2,a3, (BB) + offA2);                                    \
        MMAROW(2)                                                             \
    }                                                                         \
    {   uint32_t a0,a1,a2,a3;                                                 \
        ldm_x4(a0,a1,a2,a3, (BB) + offA3);                                    \
        MMAROW(3)                                                             \
    }                                                                         \
} while (0)

template <int KDIM, int NTOT, bool FIRST>
__global__ __launch_bounds__(256, 2) void moe_gemm_mma(
    const float* __restrict__ xsrc,      // x for FIRST (else unused)
    const float* __restrict__ W,         // [E][KDIM][NTOT] fp32
    const float* __restrict__ bias)      // [E][NTOT] fp32
{
    constexpr int NS = KDIM / 16;
    int e = blockIdx.z;
    int seg0 = g_off[e];
    int M = g_off[e + 1] - seg0;
    int rowTile = blockIdx.y * 128;       // colTile-fastest grid (L2 reuse)
    if (rowTile >= M) return;
    int colTile = blockIdx.x * 128;

    __shared__ __align__(128) char sbuf[2][BUF_BYTES];   // 24 KB

    int tid = threadIdx.x, wid = tid >> 5, lane = tid & 31;
    const float* srcA = FIRST ? xsrc : g_Hbuf;

    // ---- per-thread loader constants ----
    // A: row = tid>>1 (0..127), k-half = tid&1 (8 floats, 2 float4)
    int arow = tid >> 1, ac = tid & 1;
    int rA_g = rowTile + arow;
    int groff;
    if (FIRST) {
        groff = ((rA_g < M) ? g_tok[seg0 + rA_g] : g_tok[seg0]) * KDIM;
    } else {
        groff = (seg0 + ((rA_g < M) ? rA_g : 0)) * KDIM;
    }
    const float* pA = srcA + groff + ac * 8;
    uint32_t sAo = a16_off(arow, ac);
    // B (n-major gather): n = tid>>1 (0..127), k-half = tid&1 -> 8 strided
    // scalar loads (coalesced across the warp).
    int bn = tid >> 1, bkh = tid & 1;
    const float* pB = W + ((size_t)e * KDIM + bkh * 8) * NTOT + colTile + bn;
    uint32_t sBo = a16_off(bn, bkh);

    // ---- ldmatrix offsets ----
    int warpM = (wid & 1) * 64;
    int warpN = (wid >> 1) * 32;
    int lrow = lane & 15, lch = lane >> 4;
    uint32_t offA0 = a16_off(warpM + 0  + lrow, lch);
    uint32_t offA1 = a16_off(warpM + 16 + lrow, lch);
    uint32_t offA2 = a16_off(warpM + 32 + lrow, lch);
    uint32_t offA3 = a16_off(warpM + 48 + lrow, lch);
    // B non-trans: {r0,r1} = n0-7 frag, {r2,r3} = n8-15 frag.
    int brow = (lane & 7) + ((lane >> 4) << 3);
    int bch = (lane >> 3) & 1;
    uint32_t offB0 = a16_off(warpN + brow, bch);
    uint32_t offB1 = a16_off(warpN + 16 + brow, bch);

    float acc[4][4][4];
#pragma unroll
    for (int i = 0; i < 4; i++)
#pragma unroll
        for (int j = 0; j < 4; j++)
#pragma unroll
            for (int q = 0; q < 4; q++) acc[i][j][q] = 0.f;

    uint32_t sb0 = smem_u32(sbuf);
    float4 ra0, ra1;
    float rb0, rb1, rb2, rb3, rb4, rb5, rb6, rb7;

    // prologue
    LOADG();
    STORES(sb0);
    LOADG();
    __syncthreads();

    for (int s = 0; s < NS; s++) {
        uint32_t cur = sb0 + (uint32_t)(s & 1) * BUF_BYTES;
        uint32_t nxt = sb0 + (uint32_t)((s + 1) & 1) * BUF_BYTES;
        if (s + 1 < NS) STORES(nxt);
        if (s + 2 < NS) LOADG();
        KSTEP16(cur);
        __syncthreads();
    }

    // ----- epilogue -----
    const float* bcolBase = bias + (size_t)e * NTOT + colTile;
#pragma unroll
    for (int i = 0; i < 4; i++) {
        int r0e = warpM + i * 16 + (lane >> 2);
#pragma unroll
        for (int h = 0; h < 2; h++) {
            int grow = rowTile + r0e + h * 8;
            if (grow >= M) continue;
            size_t orow = (size_t)(seg0 + grow) * NTOT + colTile;
#pragma unroll
            for (int j = 0; j < 4; j++) {
                int col = warpN + j * 8 + (lane & 3) * 2;
                float v0 = acc[i][j][2 * h]     + bcolBase[col];
                float v1 = acc[i][j][2 * h + 1] + bcolBase[col + 1];
                if (FIRST) {
                    v0 = gelu_f(v0); v1 = gelu_f(v1);
                    *(float2*)(g_Hbuf + orow + col) = make_float2(v0, v1);
                } else {
                    *(float2*)(g_Ybuf + orow + col) = make_float2(v0, v1);
                }
            }
        }
    }
}

// ------------------------------- combine -----------------------------------
__global__ __launch_bounds__(256) void combine_kernel(float* __restrict__ out, int T) {
    size_t i = (size_t)blockIdx.x * 256 + threadIdx.x;
    size_t total = (size_t)T * (D_DIM / 4);
    if (i >= total) return;
    int t  = (int)(i >> 8);
    int d4 = (int)(i & 255);
    float w0 = g_w2[2 * t], w1 = g_w2[2 * t + 1];
    int s0 = g_slot[2 * t], s1 = g_slot[2 * t + 1];
    float4 a = ((const float4*)(g_Ybuf + (size_t)s0 * D_DIM))[d4];
    float4 b = ((const float4*)(g_Ybuf + (size_t)s1 * D_DIM))[d4];
    float4 o;
    o.x = w0 * a.x + w1 * b.x;
    o.y = w0 * a.y + w1 * b.y;
    o.z = w0 * a.z + w1 * b.z;
    o.w = w0 * a.w + w1 * b.w;
    ((float4*)(out + (size_t)t * D_DIM))[d4] = o;
}

// ------------------------------- launch ------------------------------------
extern "C" void kernel_launch(void* const* d_in, const int* in_sizes, int n_in,
                              void* d_out, int out_size)
{
    const float* x  = (const float*)d_in[0];
    const float* Wg = (const float*)d_in[1];
    const float* W1 = (const float*)d_in[2];
    const float* b1 = (const float*)d_in[3];
    const float* W2 = (const float*)d_in[4];
    const float* b2 = (const float*)d_in[5];
    float* out = (float*)d_out;

    int T = in_sizes[0] / D_DIM;
    if (T > MAXT) T = MAXT;

    int nblk = (T + 7) / 8;
    router_kernel<<<nblk, 256>>>(x, Wg, T);
    reduce_kernel<<<1, 32>>>(nblk, T, out + (size_t)T * D_DIM);
    scatter_kernel<<<(T + 255) / 256, 256>>>(T);

    int rowTilesMax = (T + 127) / 128;   // worst case: one expert takes all
    // colTile-fastest grid: concurrent CTAs share A/H rows; W stays in L2
    moe_gemm_mma<D_DIM, H_DIM, true ><<<dim3(H_DIM / 128, rowTilesMax, NE), 256>>>(x, W1, b1);
    moe_gemm_mma<H_DIM, D_DIM, false><<<dim3(D_DIM / 128, rowTilesMax, NE), 256>>>(nullptr, W2, b2);

    combine_kernel<<<(unsigned)(((size_t)T * 256 + 255) / 256), 256>>>(out, T);
}